// round 6
// baseline (speedup 1.0000x reference)
#include <cuda_runtime.h>
#include <cuda_bf16.h>
#include <math.h>

#define NQ 512
#define DM 1024
#define NEL (NQ * DM)

// ---------------- scratch ----------------
__device__ float    g_txt[NEL];           // f32 (residual)
__device__ float    g_img[NEL];
__device__ unsigned g_txt_tf[NEL];        // tf32 copies (GEMM A inputs)
__device__ unsigned g_img_tf[NEL];
__device__ float    g_Q[2][NEL];
__device__ float    g_K[2][NEL];
__device__ float    g_V[2][NEL];
__device__ unsigned g_O_tf[2][NEL];       // attention out, tf32
__device__ unsigned g_w_tf[10][DM * DM];
__device__ unsigned g_cap_tf[NQ * 768];
__device__ unsigned g_im_tf[NEL];

__device__ __forceinline__ unsigned f2tf32(float x) {
    unsigned u;
    asm("cvt.rna.tf32.f32 %0, %1;" : "=r"(u) : "f"(x));
    return u;
}
__device__ __forceinline__ uint4 cvt4(float4 v) {
    return make_uint4(f2tf32(v.x), f2tf32(v.y), f2tf32(v.z), f2tf32(v.w));
}

// ---------------- bulk f32 -> tf32 conversion ----------------
struct ConvArgs {
    const float* src[12];
    unsigned*    dst[12];
    int          n4[12];
};

__global__ __launch_bounds__(256) void conv_tf32_kernel(ConvArgs a) {
    const int z = blockIdx.y;
    const float4* __restrict__ s = (const float4*)a.src[z];
    uint4* __restrict__ d = (uint4*)a.dst[z];
    const int n4 = a.n4[z];
    for (int i = blockIdx.x * blockDim.x + threadIdx.x; i < n4; i += gridDim.x * blockDim.x)
        d[i] = cvt4(s[i]);
}

// ---------------------------------------------------------------------------
// tf32 GEMM (pre-converted inputs), BM=BN=64, BK=32, 128 thr, cp.async x3.
// ---------------------------------------------------------------------------
struct GemmArgs {
    const unsigned* A[6];
    const unsigned* W[6];
    const float*    bias[6];
    const float*    resid[6];
    float*          C[6];
    unsigned*       Ctf[6];
    int             K[6];
};

#define NSTAGE 3
#define TILE_WORDS (64 * 36)

__device__ __forceinline__ void cp_async16(unsigned smem_addr, const void* gptr) {
    asm volatile("cp.async.cg.shared.global [%0], [%1], 16;" :: "r"(smem_addr), "l"(gptr));
}
__device__ __forceinline__ void cp_commit() { asm volatile("cp.async.commit_group;"); }
__device__ __forceinline__ void cp_wait1()  { asm volatile("cp.async.wait_group 1;"); }

extern __shared__ unsigned smem_dyn[];

__global__ __launch_bounds__(128) void gemm_tf32_kernel(GemmArgs args) {
    const int z = blockIdx.z;
    const unsigned* __restrict__ A = args.A[z];
    const unsigned* __restrict__ W = args.W[z];
    const float* __restrict__ bias = args.bias[z];
    const float* __restrict__ resid = args.resid[z];
    float* __restrict__ C = args.C[z];
    unsigned* __restrict__ Ctf = args.Ctf[z];
    const int K = args.K[z];
    const int T = K >> 5;

    const int m0 = blockIdx.y * 64;
    const int n0 = blockIdx.x * 64;

    unsigned* As = smem_dyn;
    unsigned* Ws = smem_dyn + NSTAGE * TILE_WORDS;

    const int tid  = threadIdx.x;
    const int lane = tid & 31;
    const int wid  = tid >> 5;
    const int wm   = (wid & 1) * 32;
    const int wn   = (wid >> 1) * 32;
    const int g    = lane >> 2;
    const int tg   = lane & 3;

    const int r0l = tid >> 3;
    const int ql  = tid & 7;

    unsigned sA_base, sW_base;
    {
        unsigned base = (unsigned)__cvta_generic_to_shared(smem_dyn);
        sA_base = base + (r0l * 36 + ql * 4) * 4;
        sW_base = base + (NSTAGE * TILE_WORDS + r0l * 36 + ql * 4) * 4;
    }

    float acc[2][4][4];
#pragma unroll
    for (int mt = 0; mt < 2; mt++)
#pragma unroll
        for (int nt = 0; nt < 4; nt++)
#pragma unroll
            for (int r = 0; r < 4; r++) acc[mt][nt][r] = 0.f;

    auto issue = [&](int t, int st) {
        const int k0 = t * 32 + ql * 4;
        const unsigned soffA = sA_base + st * TILE_WORDS * 4;
        const unsigned soffW = sW_base + st * TILE_WORDS * 4;
#pragma unroll
        for (int it = 0; it < 4; it++) {
            cp_async16(soffA + it * 16 * 36 * 4, A + (m0 + r0l + it * 16) * K + k0);
            cp_async16(soffW + it * 16 * 36 * 4, W + (n0 + r0l + it * 16) * K + k0);
        }
    };

    issue(0, 0); cp_commit();
    if (T > 1) issue(1, 1);
    cp_commit();

    int st = 0;
    for (int t = 0; t < T; t++) {
        cp_wait1();
        __syncthreads();

        if (t + 2 < T) issue(t + 2, (st + 2) % NSTAGE);
        cp_commit();

        const unsigned* Ab = As + st * TILE_WORDS;
        const unsigned* Wb = Ws + st * TILE_WORDS;

#pragma unroll
        for (int ks = 0; ks < 4; ks++) {
            const int kb = ks * 8;
            unsigned a[2][4], b[4][2];
#pragma unroll
            for (int mt = 0; mt < 2; mt++) {
                int row = wm + mt * 16 + g;
                a[mt][0] = Ab[row * 36 + kb + tg];
                a[mt][1] = Ab[(row + 8) * 36 + kb + tg];
                a[mt][2] = Ab[row * 36 + kb + tg + 4];
                a[mt][3] = Ab[(row + 8) * 36 + kb + tg + 4];
            }
#pragma unroll
            for (int nt = 0; nt < 4; nt++) {
                int n = wn + nt * 8 + g;
                b[nt][0] = Wb[n * 36 + kb + tg];
                b[nt][1] = Wb[n * 36 + kb + tg + 4];
            }
#pragma unroll
            for (int mt = 0; mt < 2; mt++)
#pragma unroll
                for (int nt = 0; nt < 4; nt++) {
                    asm volatile(
                        "mma.sync.aligned.m16n8k8.row.col.f32.tf32.tf32.f32 "
                        "{%0,%1,%2,%3}, {%4,%5,%6,%7}, {%8,%9}, {%0,%1,%2,%3};"
                        : "+f"(acc[mt][nt][0]), "+f"(acc[mt][nt][1]),
                          "+f"(acc[mt][nt][2]), "+f"(acc[mt][nt][3])
                        : "r"(a[mt][0]), "r"(a[mt][1]), "r"(a[mt][2]), "r"(a[mt][3]),
                          "r"(b[nt][0]), "r"(b[nt][1]));
                }
        }
        st = (st + 1) % NSTAGE;
    }

#pragma unroll
    for (int mt = 0; mt < 2; mt++) {
#pragma unroll
        for (int nt = 0; nt < 4; nt++) {
            int row0 = m0 + wm + mt * 16 + g;
            int col  = n0 + wn + nt * 8 + tg * 2;
            float b0 = bias[col], b1 = bias[col + 1];
            float2 v0 = make_float2(acc[mt][nt][0] + b0, acc[mt][nt][1] + b1);
            float2 v1 = make_float2(acc[mt][nt][2] + b0, acc[mt][nt][3] + b1);
            if (resid) {
                float2 r0 = *(const float2*)(resid + row0 * DM + col);
                float2 r1 = *(const float2*)(resid + (row0 + 8) * DM + col);
                v0.x += r0.x; v0.y += r0.y;
                v1.x += r1.x; v1.y += r1.y;
            }
            *(float2*)(C + row0 * DM + col)       = v0;
            *(float2*)(C + (row0 + 8) * DM + col) = v1;
            if (Ctf) {
                *(uint2*)(Ctf + row0 * DM + col) = make_uint2(f2tf32(v0.x), f2tf32(v0.y));
                *(uint2*)(Ctf + (row0 + 8) * DM + col) = make_uint2(f2tf32(v1.x), f2tf32(v1.y));
            }
        }
    }
}

// ---------------------------------------------------------------------------
// sliding-window attention, restructured score phase:
// warp = (query i, head h). lane = (sgrp = lane>>3 -> slot-in-round,
// j = lane&7 -> 16 dims). 4 slots reduced per round via 3-shfl butterfly.
// ---------------------------------------------------------------------------
__global__ __launch_bounds__(256) void swattn_kernel(
        const float* __restrict__ kb0, const float* __restrict__ vb0,
        const float* __restrict__ kb1, const float* __restrict__ vb1) {
    const int a = blockIdx.y;
    const int i = blockIdx.x;
    const int h = threadIdx.x >> 5;
    const int lane = threadIdx.x & 31;
    const int tid = threadIdx.x;

    const float* __restrict__ Q  = g_Q[a];
    const float* __restrict__ Kc = g_K[a];
    const float* __restrict__ Vc = g_V[a];
    const float* __restrict__ kb = a ? kb1 : kb0;
    const float* __restrict__ vb = a ? vb1 : vb0;

    __shared__ float qs[DM];
    __shared__ float sc[8][68];

    // stage q row
    ((float4*)qs)[tid] = ((const float4*)(Q + i * DM))[tid];
    __syncthreads();

    const float scale = 0.08838834764831845f;  // 1/sqrt(128)
    const int lo = i - 32;
    const int p_start = max(0, 32 - i);
    const int p_end   = min(66, 544 - i);
    const int invalid = 66 - (p_end - p_start);
    const int n_pad   = max(0, invalid - 2);

    const int j    = lane & 7;    // dim group: 16 dims
    const int sgrp = lane >> 3;   // slot within round

    // q fragment for this head, dims j*16 .. j*16+15
    const float* qp = qs + h * 128 + j * 16;
    float4 q0 = *(const float4*)(qp + 0);
    float4 q1 = *(const float4*)(qp + 4);
    float4 q2 = *(const float4*)(qp + 8);
    float4 q3 = *(const float4*)(qp + 12);

    // ---- scores: 17 rounds x 4 slots ----
#pragma unroll 4
    for (int pb = 0; pb < 68; pb += 4) {
        const int p = pb + sgrp;
        const bool valid = (p >= p_start) & (p < p_end);
        float acc = 0.f;
        if (valid) {
            const float* kr = Kc + (lo + p) * DM + h * 128 + j * 16;
            float4 k0 = *(const float4*)(kr + 0);
            float4 k1 = *(const float4*)(kr + 4);
            float4 k2 = *(const float4*)(kr + 8);
            float4 k3 = *(const float4*)(kr + 12);
            acc = q0.x * k0.x + q0.y * k0.y + q0.z * k0.z + q0.w * k0.w
                + q1.x * k1.x + q1.y * k1.y + q1.z * k1.z + q1.w * k1.w
                + q2.x * k2.x + q2.y * k2.y + q2.z * k2.z + q2.w * k2.w
                + q3.x * k3.x + q3.y * k3.y + q3.z * k3.z + q3.w * k3.w;
        }
        acc += __shfl_xor_sync(0xffffffffu, acc, 1);
        acc += __shfl_xor_sync(0xffffffffu, acc, 2);
        acc += __shfl_xor_sync(0xffffffffu, acc, 4);
        if (j == 0 && p < 66) sc[h][p] = valid ? acc * scale : -1e30f;
    }

    // ---- pad score ----
    float s_pad = -1e30f;
    if (n_pad > 0) {
        const float* kr = kb + h * 128 + j * 16;
        float4 k0 = *(const float4*)(kr + 0);
        float4 k1 = *(const float4*)(kr + 4);
        float4 k2 = *(const float4*)(kr + 8);
        float4 k3 = *(const float4*)(kr + 12);
        float acc = q0.x * k0.x + q0.y * k0.y + q0.z * k0.z + q0.w * k0.w
                  + q1.x * k1.x + q1.y * k1.y + q1.z * k1.z + q1.w * k1.w
                  + q2.x * k2.x + q2.y * k2.y + q2.z * k2.z + q2.w * k2.w
                  + q3.x * k3.x + q3.y * k3.y + q3.z * k3.z + q3.w * k3.w;
        acc += __shfl_xor_sync(0xffffffffu, acc, 1);
        acc += __shfl_xor_sync(0xffffffffu, acc, 2);
        acc += __shfl_xor_sync(0xffffffffu, acc, 4);
        s_pad = acc * scale;
    }
    __syncwarp();

    // ---- softmax over 66 slots (+ pad group) ----
    float v0 = sc[h][lane];                               // p = 0..31
    float v1 = sc[h][lane + 32];                          // p = 32..63
    float v2 = (lane < 2) ? sc[h][lane + 64] : -1e30f;    // p = 64,65

    float mloc = fmaxf(fmaxf(v0, v1), v2);
    if (n_pad > 0) mloc = fmaxf(mloc, s_pad);
#pragma unroll
    for (int off = 16; off > 0; off >>= 1)
        mloc = fmaxf(mloc, __shfl_xor_sync(0xffffffffu, mloc, off));
    const float m = mloc;

    float e0 = expf(v0 - m);
    float e1 = expf(v1 - m);
    float e2 = (lane < 2) ? expf(v2 - m) : 0.f;
    float dloc = e0 + e1 + e2;
#pragma unroll
    for (int off = 16; off > 0; off >>= 1)
        dloc += __shfl_xor_sync(0xffffffffu, dloc, off);
    float w_pad = (n_pad > 0) ? (float)n_pad * expf(s_pad - m) : 0.f;
    const float inv = 1.f / (dloc + w_pad);

    sc[h][lane]      = e0 * inv;
    sc[h][lane + 32] = e1 * inv;
    if (lane < 2) sc[h][lane + 64] = e2 * inv;
    __syncwarp();

    // ---- weighted V sum (coalesced) ----
    const int base = h * 128 + lane * 4;
    float4 acc4 = make_float4(0.f, 0.f, 0.f, 0.f);
    for (int p = p_start; p < p_end; p++) {
        const float w = sc[h][p];
        const float4 v4 = *(const float4*)(Vc + (lo + p) * DM + base);
        acc4.x += w * v4.x; acc4.y += w * v4.y;
        acc4.z += w * v4.z; acc4.w += w * v4.w;
    }
    if (n_pad > 0) {
        const float wp = w_pad * inv;
        const float4 vb4 = *(const float4*)(vb + base);
        acc4.x += wp * vb4.x; acc4.y += wp * vb4.y;
        acc4.z += wp * vb4.z; acc4.w += wp * vb4.w;
    }
    *(uint4*)(g_O_tf[a] + i * DM + base) = cvt4(acc4);
}

// ---------------------------------------------------------------------------
extern "C" void kernel_launch(void* const* d_in, const int* in_sizes, int n_in,
                              void* d_out, int out_size) {
    (void)in_sizes; (void)n_in; (void)out_size;

    const float* images   = (const float*)d_in[0];
    const float* captions = (const float*)d_in[1];
    const float* tp_w = (const float*)d_in[3];
    const float* tp_b = (const float*)d_in[4];
    const float* ip_w = (const float*)d_in[5];
    const float* ip_b = (const float*)d_in[6];
    const float* ia[8]; for (int k = 0; k < 8; k++) ia[k] = (const float*)d_in[7 + k];
    const float* ta[8]; for (int k = 0; k < 8; k++) ta[k] = (const float*)d_in[15 + k];
    float* out = (float*)d_out;

    float *txt, *img, *Qb, *Kb, *Vb;
    unsigned *txt_tf, *img_tf, *Otf, *wtf, *cap_tf, *im_tf;
    cudaGetSymbolAddress((void**)&txt, g_txt);
    cudaGetSymbolAddress((void**)&img, g_img);
    cudaGetSymbolAddress((void**)&txt_tf, g_txt_tf);
    cudaGetSymbolAddress((void**)&img_tf, g_img_tf);
    cudaGetSymbolAddress((void**)&Qb, g_Q);
    cudaGetSymbolAddress((void**)&Kb, g_K);
    cudaGetSymbolAddress((void**)&Vb, g_V);
    cudaGetSymbolAddress((void**)&Otf, g_O_tf);
    cudaGetSymbolAddress((void**)&wtf, g_w_tf);
    cudaGetSymbolAddress((void**)&cap_tf, g_cap_tf);
    cudaGetSymbolAddress((void**)&im_tf, g_im_tf);

    unsigned* wts[10];
    for (int s = 0; s < 10; s++) wts[s] = wtf + s * (DM * DM);

    // ---- launch 0: bulk tf32 conversion ----
    {
        ConvArgs ca{};
        const float* srcs[12] = { tp_w, ip_w, ia[0], ia[2], ia[4], ia[6],
                                  ta[0], ta[2], ta[4], ta[6], captions, images };
        unsigned*    dsts[12] = { wts[0], wts[1], wts[2], wts[3], wts[4], wts[5],
                                  wts[6], wts[7], wts[8], wts[9], cap_tf, im_tf };
        int ns[12] = { DM * 768, DM * DM, DM * DM, DM * DM, DM * DM, DM * DM,
                       DM * DM, DM * DM, DM * DM, DM * DM, NQ * 768, NQ * DM };
        for (int s = 0; s < 12; s++) { ca.src[s] = srcs[s]; ca.dst[s] = dsts[s]; ca.n4[s] = ns[s] / 4; }
        conv_tf32_kernel<<<dim3(64, 12), 256>>>(ca);
    }

    const dim3 blk(128);
    const int GX = DM / 64;   // 16
    const int GY = NQ / 64;   // 8
    const int SMEM = NSTAGE * TILE_WORDS * 2 * 4;
    cudaFuncSetAttribute(gemm_tf32_kernel, cudaFuncAttributeMaxDynamicSharedMemorySize, SMEM);

    // ---- launch 1: input projections (z=2) ----
    {
        GemmArgs ar{};
        ar.A[0] = cap_tf; ar.W[0] = wts[0]; ar.bias[0] = tp_b; ar.resid[0] = nullptr;
        ar.C[0] = txt; ar.Ctf[0] = txt_tf; ar.K[0] = 768;
        ar.A[1] = im_tf;  ar.W[1] = wts[1]; ar.bias[1] = ip_b; ar.resid[1] = nullptr;
        ar.C[1] = img; ar.Ctf[1] = img_tf; ar.K[1] = 1024;
        gemm_tf32_kernel<<<dim3(GX, GY, 2), blk, SMEM>>>(ar);
    }

    // ---- launch 2: six QKV projections (z=6) ----
    {
        GemmArgs ar{};
        const unsigned* Aarr[6] = { img_tf, txt_tf, txt_tf, txt_tf, img_tf, img_tf };
        const unsigned* Warr[6] = { wts[2], wts[3], wts[4], wts[6], wts[7], wts[8] };
        const float*    Barr[6] = { ia[1], ia[3], ia[5], ta[1], ta[3], ta[5] };
        float*          Carr[6] = { Qb, Kb, Vb, Qb + NEL, Kb + NEL, Vb + NEL };
        for (int s = 0; s < 6; s++) {
            ar.A[s] = Aarr[s]; ar.W[s] = Warr[s]; ar.bias[s] = Barr[s];
            ar.resid[s] = nullptr; ar.C[s] = Carr[s]; ar.Ctf[s] = nullptr; ar.K[s] = 1024;
        }
        gemm_tf32_kernel<<<dim3(GX, GY, 6), blk, SMEM>>>(ar);
    }

    // ---- launch 3: sliding-window attention ----
    swattn_kernel<<<dim3(NQ, 2), 256>>>(ia[3], ia[5], ta[3], ta[5]);

    // ---- launch 4: output projections + residual (z=2) ----
    {
        GemmArgs ar{};
        ar.A[0] = Otf;       ar.W[0] = wts[5]; ar.bias[0] = ia[7]; ar.resid[0] = img;
        ar.C[0] = out;       ar.Ctf[0] = nullptr; ar.K[0] = 1024;
        ar.A[1] = Otf + NEL; ar.W[1] = wts[9]; ar.bias[1] = ta[7]; ar.resid[1] = txt;
        ar.C[1] = out + NEL; ar.Ctf[1] = nullptr; ar.K[1] = 1024;
        gemm_tf32_kernel<<<dim3(GX, GY, 2), blk, SMEM>>>(ar);
    }
}

// round 8
// speedup vs baseline: 1.2135x; 1.2135x over previous
#include <cuda_runtime.h>
#include <cuda_bf16.h>
#include <math.h>

#define NQ 512
#define DM 1024
#define NEL (NQ * DM)

// ---------------- scratch ----------------
__device__ float    g_txt[NEL];           // f32 (residual)
__device__ float    g_img[NEL];
__device__ unsigned g_txt_tf[NEL];        // tf32 copies (GEMM A inputs)
__device__ unsigned g_img_tf[NEL];
__device__ float    g_Q[2][NEL];
__device__ float    g_K[2][NEL];
__device__ float    g_V[2][NEL];
__device__ unsigned g_O_tf[2][NEL];       // attention out, tf32
__device__ unsigned g_w_tf[10][DM * DM];
__device__ unsigned g_cap_tf[NQ * 768];
__device__ unsigned g_im_tf[NEL];

__device__ __forceinline__ unsigned f2tf32(float x) {
    unsigned u;
    asm("cvt.rna.tf32.f32 %0, %1;" : "=r"(u) : "f"(x));
    return u;
}
__device__ __forceinline__ uint4 cvt4(float4 v) {
    return make_uint4(f2tf32(v.x), f2tf32(v.y), f2tf32(v.z), f2tf32(v.w));
}

// ---------------- bulk f32 -> tf32 conversion ----------------
struct ConvArgs {
    const float* src[12];
    unsigned*    dst[12];
    int          n4[12];
};

__global__ __launch_bounds__(256) void conv_tf32_kernel(ConvArgs a) {
    const int z = blockIdx.y;
    const float4* __restrict__ s = (const float4*)a.src[z];
    uint4* __restrict__ d = (uint4*)a.dst[z];
    const int n4 = a.n4[z];
    for (int i = blockIdx.x * blockDim.x + threadIdx.x; i < n4; i += gridDim.x * blockDim.x)
        d[i] = cvt4(s[i]);
}

// ---------------------------------------------------------------------------
// tf32 GEMM (pre-converted inputs), BM=BN=64, BK=32, 128 thr, cp.async x3.
// ---------------------------------------------------------------------------
struct GemmArgs {
    const unsigned* A[6];
    const unsigned* W[6];
    const float*    bias[6];
    const float*    resid[6];
    float*          C[6];
    unsigned*       Ctf[6];
    int             K[6];
};

#define NSTAGE 3
#define TILE_WORDS (64 * 36)

__device__ __forceinline__ void cp_async16(unsigned smem_addr, const void* gptr) {
    asm volatile("cp.async.cg.shared.global [%0], [%1], 16;" :: "r"(smem_addr), "l"(gptr));
}
__device__ __forceinline__ void cp_commit() { asm volatile("cp.async.commit_group;"); }
__device__ __forceinline__ void cp_wait1()  { asm volatile("cp.async.wait_group 1;"); }

extern __shared__ unsigned smem_dyn[];

__global__ __launch_bounds__(128) void gemm_tf32_kernel(GemmArgs args) {
    const int z = blockIdx.z;
    const unsigned* __restrict__ A = args.A[z];
    const unsigned* __restrict__ W = args.W[z];
    const float* __restrict__ bias = args.bias[z];
    const float* __restrict__ resid = args.resid[z];
    float* __restrict__ C = args.C[z];
    unsigned* __restrict__ Ctf = args.Ctf[z];
    const int K = args.K[z];
    const int T = K >> 5;

    const int m0 = blockIdx.y * 64;
    const int n0 = blockIdx.x * 64;

    unsigned* As = smem_dyn;
    unsigned* Ws = smem_dyn + NSTAGE * TILE_WORDS;

    const int tid  = threadIdx.x;
    const int lane = tid & 31;
    const int wid  = tid >> 5;
    const int wm   = (wid & 1) * 32;
    const int wn   = (wid >> 1) * 32;
    const int g    = lane >> 2;
    const int tg   = lane & 3;

    const int r0l = tid >> 3;
    const int ql  = tid & 7;

    unsigned sA_base, sW_base;
    {
        unsigned base = (unsigned)__cvta_generic_to_shared(smem_dyn);
        sA_base = base + (r0l * 36 + ql * 4) * 4;
        sW_base = base + (NSTAGE * TILE_WORDS + r0l * 36 + ql * 4) * 4;
    }

    float acc[2][4][4];
#pragma unroll
    for (int mt = 0; mt < 2; mt++)
#pragma unroll
        for (int nt = 0; nt < 4; nt++)
#pragma unroll
            for (int r = 0; r < 4; r++) acc[mt][nt][r] = 0.f;

    auto issue = [&](int t, int st) {
        const int k0 = t * 32 + ql * 4;
        const unsigned soffA = sA_base + st * TILE_WORDS * 4;
        const unsigned soffW = sW_base + st * TILE_WORDS * 4;
#pragma unroll
        for (int it = 0; it < 4; it++) {
            cp_async16(soffA + it * 16 * 36 * 4, A + (m0 + r0l + it * 16) * K + k0);
            cp_async16(soffW + it * 16 * 36 * 4, W + (n0 + r0l + it * 16) * K + k0);
        }
    };

    issue(0, 0); cp_commit();
    if (T > 1) issue(1, 1);
    cp_commit();

    int st = 0;
    for (int t = 0; t < T; t++) {
        cp_wait1();
        __syncthreads();

        if (t + 2 < T) issue(t + 2, (st + 2) % NSTAGE);
        cp_commit();

        const unsigned* Ab = As + st * TILE_WORDS;
        const unsigned* Wb = Ws + st * TILE_WORDS;

#pragma unroll
        for (int ks = 0; ks < 4; ks++) {
            const int kb = ks * 8;
            unsigned a[2][4], b[4][2];
#pragma unroll
            for (int mt = 0; mt < 2; mt++) {
                int row = wm + mt * 16 + g;
                a[mt][0] = Ab[row * 36 + kb + tg];
                a[mt][1] = Ab[(row + 8) * 36 + kb + tg];
                a[mt][2] = Ab[row * 36 + kb + tg + 4];
                a[mt][3] = Ab[(row + 8) * 36 + kb + tg + 4];
            }
#pragma unroll
            for (int nt = 0; nt < 4; nt++) {
                int n = wn + nt * 8 + g;
                b[nt][0] = Wb[n * 36 + kb + tg];
                b[nt][1] = Wb[n * 36 + kb + tg + 4];
            }
#pragma unroll
            for (int mt = 0; mt < 2; mt++)
#pragma unroll
                for (int nt = 0; nt < 4; nt++) {
                    asm volatile(
                        "mma.sync.aligned.m16n8k8.row.col.f32.tf32.tf32.f32 "
                        "{%0,%1,%2,%3}, {%4,%5,%6,%7}, {%8,%9}, {%0,%1,%2,%3};"
                        : "+f"(acc[mt][nt][0]), "+f"(acc[mt][nt][1]),
                          "+f"(acc[mt][nt][2]), "+f"(acc[mt][nt][3])
                        : "r"(a[mt][0]), "r"(a[mt][1]), "r"(a[mt][2]), "r"(a[mt][3]),
                          "r"(b[nt][0]), "r"(b[nt][1]));
                }
        }
        st = (st + 1) % NSTAGE;
    }

#pragma unroll
    for (int mt = 0; mt < 2; mt++) {
#pragma unroll
        for (int nt = 0; nt < 4; nt++) {
            int row0 = m0 + wm + mt * 16 + g;
            int col  = n0 + wn + nt * 8 + tg * 2;
            float b0 = bias[col], b1 = bias[col + 1];
            float2 v0 = make_float2(acc[mt][nt][0] + b0, acc[mt][nt][1] + b1);
            float2 v1 = make_float2(acc[mt][nt][2] + b0, acc[mt][nt][3] + b1);
            if (resid) {
                float2 r0 = *(const float2*)(resid + row0 * DM + col);
                float2 r1 = *(const float2*)(resid + (row0 + 8) * DM + col);
                v0.x += r0.x; v0.y += r0.y;
                v1.x += r1.x; v1.y += r1.y;
            }
            *(float2*)(C + row0 * DM + col)       = v0;
            *(float2*)(C + (row0 + 8) * DM + col) = v1;
            if (Ctf) {
                *(uint2*)(Ctf + row0 * DM + col) = make_uint2(f2tf32(v0.x), f2tf32(v0.y));
                *(uint2*)(Ctf + (row0 + 8) * DM + col) = make_uint2(f2tf32(v1.x), f2tf32(v1.y));
            }
        }
    }
}

// ---------------------------------------------------------------------------
// CTA-tiled sliding-window attention.
// CTA = (64 queries, 1 head). Stage Q(64x128), K/V band (129 rows + pad row
// kb/vb = 130x128) in smem once. Score GEMM over the band (+pad col j=129),
// quad-per-query softmax into zeroed weight matrix W (aliases Q buffer),
// V GEMM over the band. Writes tf32 output.
// Layout (16B-alignment): Vs[130][136] @0, Qs/S[64][136] next (both float4-
// accessed, offsets are 16B multiples), Ks[130][133] LAST (scalar access only).
// ---------------------------------------------------------------------------
#define KPAD 133
#define VPAD 136
#define QPAD 136
#define ATT_SMEM ((130 * VPAD + 64 * QPAD + 130 * KPAD) * 4)

extern __shared__ float att_sm[];

__global__ __launch_bounds__(256, 1) void swattn_tiled(
        const float* __restrict__ kb0, const float* __restrict__ vb0,
        const float* __restrict__ kb1, const float* __restrict__ vb1) {
    float* Vs = att_sm;                        // [130][136]  (float4, aligned)
    float* Qs = att_sm + 130 * VPAD;           // [64][136]   (float4, aligned)
    float* Ks = Qs + 64 * QPAD;                // [130][133]  (scalar only)
    float* S  = Qs;

    const int a  = blockIdx.z;
    const int h  = blockIdx.y;
    const int i0 = blockIdx.x * 64;
    const int idx0 = i0 - 32;
    const int tid = threadIdx.x;

    const float* __restrict__ Qg = g_Q[a];
    const float* __restrict__ Kg = g_K[a];
    const float* __restrict__ Vg = g_V[a];
    const float* __restrict__ kb = (a ? kb1 : kb0) + h * 128;
    const float* __restrict__ vb = (a ? vb1 : vb0) + h * 128;

    const float scale = 0.08838834764831845f;  // 1/sqrt(128)

    // ---- stage Q (64 x 128) ----
    for (int f = tid; f < 64 * 32; f += 256) {
        int r = f >> 5, c = f & 31;
        float4 v = *(const float4*)(Qg + (i0 + r) * DM + h * 128 + c * 4);
        *(float4*)(Qs + r * QPAD + c * 4) = v;
    }
    // ---- stage K and V bands (rows j=0..128 real, j=129 = kb/vb) ----
    for (int f = tid; f < 130 * 32; f += 256) {
        int j = f >> 5, c = f & 31;
        int gr = min(max(idx0 + j, 0), 511);
        const float* ksrc = (j < 129) ? Kg + gr * DM + h * 128 : kb;
        const float* vsrc = (j < 129) ? Vg + gr * DM + h * 128 : vb;
        float4 kv = *(const float4*)(ksrc + c * 4);
        float4 vv = *(const float4*)(vsrc + c * 4);
        Ks[j * KPAD + c * 4 + 0] = kv.x;
        Ks[j * KPAD + c * 4 + 1] = kv.y;
        Ks[j * KPAD + c * 4 + 2] = kv.z;
        Ks[j * KPAD + c * 4 + 3] = kv.w;
        *(float4*)(Vs + j * VPAD + c * 4) = vv;
    }
    __syncthreads();

    // ---- score GEMM: S[q][j] = Q[q] . Krow[j], band j in [qb, qb+79] + j=129 ----
    {
        const int ty = tid >> 4;      // 0..15 -> q block of 4
        const int tx = tid & 15;
        const int qb = ty * 4;

        int  jidx[6];
        bool jok[6];
#pragma unroll
        for (int jj = 0; jj < 5; jj++) {
            jidx[jj] = qb + tx + 16 * jj;
            jok[jj]  = (jidx[jj] < 130);
        }
        jidx[5] = 129; jok[5] = true;

        float acc[4][6];
#pragma unroll
        for (int qq = 0; qq < 4; qq++)
#pragma unroll
            for (int jj = 0; jj < 6; jj++) acc[qq][jj] = 0.f;

#pragma unroll 8
        for (int kk = 0; kk < 128; kk++) {
            float qv[4];
#pragma unroll
            for (int qq = 0; qq < 4; qq++) qv[qq] = Qs[(qb + qq) * QPAD + kk];
#pragma unroll
            for (int jj = 0; jj < 6; jj++) {
                if (jok[jj]) {
                    float kv = Ks[jidx[jj] * KPAD + kk];
#pragma unroll
                    for (int qq = 0; qq < 4; qq++) acc[qq][jj] += qv[qq] * kv;
                }
            }
        }
        __syncthreads();  // done reading Qs; S aliases it

#pragma unroll
        for (int jj = 0; jj < 6; jj++) {
            if (jok[jj] && (jj < 5 || tx == 0)) {
#pragma unroll
                for (int qq = 0; qq < 4; qq++)
                    S[(qb + qq) * QPAD + jidx[jj]] = acc[qq][jj] * scale;
            }
        }
    }
    __syncthreads();

    // ---- softmax per query (quad of 4 threads) ----
    {
        const int q = tid >> 2;
        const int s = tid & 3;
        const int i = i0 + q;
        const int p_start = max(0, 32 - i);
        const int p_end   = min(66, 544 - i);
        const int invalid = 66 - (p_end - p_start);
        const int n_pad   = max(0, invalid - 2);

        float vals[17];
        float m = -1e30f;
#pragma unroll
        for (int k = 0; k < 17; k++) {
            int p = s + 4 * k;
            bool valid = (p >= p_start) & (p < p_end);
            vals[k] = valid ? S[q * QPAD + q + p] : -1e30f;
            m = fmaxf(m, vals[k]);
        }
        float sp = S[q * QPAD + 129];
        if (n_pad > 0) m = fmaxf(m, sp);
        m = fmaxf(m, __shfl_xor_sync(0xffffffffu, m, 1));
        m = fmaxf(m, __shfl_xor_sync(0xffffffffu, m, 2));

        float d = 0.f;
#pragma unroll
        for (int k = 0; k < 17; k++) {
            int p = s + 4 * k;
            bool valid = (p >= p_start) & (p < p_end);
            float e = valid ? expf(vals[k] - m) : 0.f;
            vals[k] = e;
            d += e;
        }
        d += __shfl_xor_sync(0xffffffffu, d, 1);
        d += __shfl_xor_sync(0xffffffffu, d, 2);
        float wp = (n_pad > 0) ? (float)n_pad * expf(sp - m) : 0.f;
        const float inv = 1.f / (d + wp);

        __syncwarp();  // all quad reads of S done before zeroing
        for (int c = s * 34; c < s * 34 + 34; c++) S[q * QPAD + c] = 0.f;
        __syncwarp();

#pragma unroll
        for (int k = 0; k < 17; k++) {
            int p = s + 4 * k;
            if ((p >= p_start) & (p < p_end)) S[q * QPAD + q + p] = vals[k] * inv;
        }
        if (s == 0) S[q * QPAD + 129] = wp * inv;
    }
    __syncthreads();

    // ---- V GEMM: O[q][d] = sum_j W[q][j] * V[j][d], band + pad row ----
    {
        const int wty  = tid >> 5;     // warp -> 8 queries
        const int lane = tid & 31;     // -> 4 dims
        const int qb0  = wty * 8;

        float4 acc[8];
#pragma unroll
        for (int qq = 0; qq < 8; qq++) acc[qq] = make_float4(0.f, 0.f, 0.f, 0.f);

        for (int j = qb0; j <= qb0 + 72; j++) {   // j <= 128 always
            float4 v4 = *(const float4*)(Vs + j * VPAD + lane * 4);
#pragma unroll
            for (int qq = 0; qq < 8; qq++) {
                float w = S[(qb0 + qq) * QPAD + j];
                acc[qq].x += w * v4.x; acc[qq].y += w * v4.y;
                acc[qq].z += w * v4.z; acc[qq].w += w * v4.w;
            }
        }
        {   // pad row j = 129
            float4 v4 = *(const float4*)(Vs + 129 * VPAD + lane * 4);
#pragma unroll
            for (int qq = 0; qq < 8; qq++) {
                float w = S[(qb0 + qq) * QPAD + 129];
                acc[qq].x += w * v4.x; acc[qq].y += w * v4.y;
                acc[qq].z += w * v4.z; acc[qq].w += w * v4.w;
            }
        }
#pragma unroll
        for (int qq = 0; qq < 8; qq++) {
            *(uint4*)(g_O_tf[a] + (i0 + qb0 + qq) * DM + h * 128 + lane * 4) = cvt4(acc[qq]);
        }
    }
}

// ---------------------------------------------------------------------------
extern "C" void kernel_launch(void* const* d_in, const int* in_sizes, int n_in,
                              void* d_out, int out_size) {
    (void)in_sizes; (void)n_in; (void)out_size;

    const float* images   = (const float*)d_in[0];
    const float* captions = (const float*)d_in[1];
    const float* tp_w = (const float*)d_in[3];
    const float* tp_b = (const float*)d_in[4];
    const float* ip_w = (const float*)d_in[5];
    const float* ip_b = (const float*)d_in[6];
    const float* ia[8]; for (int k = 0; k < 8; k++) ia[k] = (const float*)d_in[7 + k];
    const float* ta[8]; for (int k = 0; k < 8; k++) ta[k] = (const float*)d_in[15 + k];
    float* out = (float*)d_out;

    float *txt, *img, *Qb, *Kb, *Vb;
    unsigned *txt_tf, *img_tf, *Otf, *wtf, *cap_tf, *im_tf;
    cudaGetSymbolAddress((void**)&txt, g_txt);
    cudaGetSymbolAddress((void**)&img, g_img);
    cudaGetSymbolAddress((void**)&txt_tf, g_txt_tf);
    cudaGetSymbolAddress((void**)&img_tf, g_img_tf);
    cudaGetSymbolAddress((void**)&Qb, g_Q);
    cudaGetSymbolAddress((void**)&Kb, g_K);
    cudaGetSymbolAddress((void**)&Vb, g_V);
    cudaGetSymbolAddress((void**)&Otf, g_O_tf);
    cudaGetSymbolAddress((void**)&wtf, g_w_tf);
    cudaGetSymbolAddress((void**)&cap_tf, g_cap_tf);
    cudaGetSymbolAddress((void**)&im_tf, g_im_tf);

    unsigned* wts[10];
    for (int s = 0; s < 10; s++) wts[s] = wtf + s * (DM * DM);

    // ---- launch 0: bulk tf32 conversion ----
    {
        ConvArgs ca{};
        const float* srcs[12] = { tp_w, ip_w, ia[0], ia[2], ia[4], ia[6],
                                  ta[0], ta[2], ta[4], ta[6], captions, images };
        unsigned*    dsts[12] = { wts[0], wts[1], wts[2], wts[3], wts[4], wts[5],
                                  wts[6], wts[7], wts[8], wts[9], cap_tf, im_tf };
        int ns[12] = { DM * 768, DM * DM, DM * DM, DM * DM, DM * DM, DM * DM,
                       DM * DM, DM * DM, DM * DM, DM * DM, NQ * 768, NQ * DM };
        for (int s = 0; s < 12; s++) { ca.src[s] = srcs[s]; ca.dst[s] = dsts[s]; ca.n4[s] = ns[s] / 4; }
        conv_tf32_kernel<<<dim3(64, 12), 256>>>(ca);
    }

    const dim3 blk(128);
    const int GX = DM / 64;   // 16
    const int GY = NQ / 64;   // 8
    const int SMEM = NSTAGE * TILE_WORDS * 2 * 4;
    cudaFuncSetAttribute(gemm_tf32_kernel, cudaFuncAttributeMaxDynamicSharedMemorySize, SMEM);
    cudaFuncSetAttribute(swattn_tiled, cudaFuncAttributeMaxDynamicSharedMemorySize, ATT_SMEM);

    // ---- launch 1: input projections (z=2) ----
    {
        GemmArgs ar{};
        ar.A[0] = cap_tf; ar.W[0] = wts[0]; ar.bias[0] = tp_b; ar.resid[0] = nullptr;
        ar.C[0] = txt; ar.Ctf[0] = txt_tf; ar.K[0] = 768;
        ar.A[1] = im_tf;  ar.W[1] = wts[1]; ar.bias[1] = ip_b; ar.resid[1] = nullptr;
        ar.C[1] = img; ar.Ctf[1] = img_tf; ar.K[1] = 1024;
        gemm_tf32_kernel<<<dim3(GX, GY, 2), blk, SMEM>>>(ar);
    }

    // ---- launch 2: six QKV projections (z=6) ----
    {
        GemmArgs ar{};
        const unsigned* Aarr[6] = { img_tf, txt_tf, txt_tf, txt_tf, img_tf, img_tf };
        const unsigned* Warr[6] = { wts[2], wts[3], wts[4], wts[6], wts[7], wts[8] };
        const float*    Barr[6] = { ia[1], ia[3], ia[5], ta[1], ta[3], ta[5] };
        float*          Carr[6] = { Qb, Kb, Vb, Qb + NEL, Kb + NEL, Vb + NEL };
        for (int s = 0; s < 6; s++) {
            ar.A[s] = Aarr[s]; ar.W[s] = Warr[s]; ar.bias[s] = Barr[s];
            ar.resid[s] = nullptr; ar.C[s] = Carr[s]; ar.Ctf[s] = nullptr; ar.K[s] = 1024;
        }
        gemm_tf32_kernel<<<dim3(GX, GY, 6), blk, SMEM>>>(ar);
    }

    // ---- launch 3: CTA-tiled sliding-window attention ----
    swattn_tiled<<<dim3(8, 8, 2), 256, ATT_SMEM>>>(ia[3], ia[5], ta[3], ta[5]);

    // ---- launch 4: output projections + residual (z=2) ----
    {
        GemmArgs ar{};
        ar.A[0] = Otf;       ar.W[0] = wts[5]; ar.bias[0] = ia[7]; ar.resid[0] = img;
        ar.C[0] = out;       ar.Ctf[0] = nullptr; ar.K[0] = 1024;
        ar.A[1] = Otf + NEL; ar.W[1] = wts[9]; ar.bias[1] = ta[7]; ar.resid[1] = txt;
        ar.C[1] = out + NEL; ar.Ctf[1] = nullptr; ar.K[1] = 1024;
        gemm_tf32_kernel<<<dim3(GX, GY, 2), blk, SMEM>>>(ar);
    }
}

// round 9
// speedup vs baseline: 1.2278x; 1.0118x over previous
#include <cuda_runtime.h>
#include <cuda_bf16.h>
#include <math.h>

#define NQ 512
#define DM 1024
#define NEL (NQ * DM)

// ---------------- scratch ----------------
__device__ float    g_txt[NEL];           // f32 (residual)
__device__ float    g_img[NEL];
__device__ unsigned g_txt_tf[NEL];        // tf32 copies (GEMM A inputs)
__device__ unsigned g_img_tf[NEL];
__device__ float    g_Q[2][NEL];
__device__ float    g_K[2][NEL];
__device__ float    g_V[2][NEL];
__device__ unsigned g_O_tf[2][NEL];       // attention out, tf32
__device__ unsigned g_w_tf[10][DM * DM];
__device__ unsigned g_cap_tf[NQ * 768];
__device__ unsigned g_im_tf[NEL];

__device__ __forceinline__ unsigned f2tf32(float x) {
    unsigned u;
    asm("cvt.rna.tf32.f32 %0, %1;" : "=r"(u) : "f"(x));
    return u;
}
__device__ __forceinline__ uint4 cvt4(float4 v) {
    return make_uint4(f2tf32(v.x), f2tf32(v.y), f2tf32(v.z), f2tf32(v.w));
}

// ---------------- bulk f32 -> tf32 conversion ----------------
struct ConvArgs {
    const float* src[12];
    unsigned*    dst[12];
    int          n4[12];
};

__global__ __launch_bounds__(256) void conv_tf32_kernel(ConvArgs a) {
    const int z = blockIdx.y;
    const float4* __restrict__ s = (const float4*)a.src[z];
    uint4* __restrict__ d = (uint4*)a.dst[z];
    const int n4 = a.n4[z];
    for (int i = blockIdx.x * blockDim.x + threadIdx.x; i < n4; i += gridDim.x * blockDim.x)
        d[i] = cvt4(s[i]);
}

// ---------------------------------------------------------------------------
// tf32 GEMM (pre-converted inputs), BM=BN=64, BK=32, 128 thr, cp.async x3.
// ---------------------------------------------------------------------------
struct GemmArgs {
    const unsigned* A[6];
    const unsigned* W[6];
    const float*    bias[6];
    const float*    resid[6];
    float*          C[6];
    unsigned*       Ctf[6];
    int             K[6];
};

#define NSTAGE 3
#define TILE_WORDS (64 * 36)

__device__ __forceinline__ void cp_async16(unsigned smem_addr, const void* gptr) {
    asm volatile("cp.async.cg.shared.global [%0], [%1], 16;" :: "r"(smem_addr), "l"(gptr));
}
__device__ __forceinline__ void cp_commit() { asm volatile("cp.async.commit_group;"); }
__device__ __forceinline__ void cp_wait1()  { asm volatile("cp.async.wait_group 1;"); }

extern __shared__ unsigned smem_dyn[];

__global__ __launch_bounds__(128) void gemm_tf32_kernel(GemmArgs args) {
    const int z = blockIdx.z;
    const unsigned* __restrict__ A = args.A[z];
    const unsigned* __restrict__ W = args.W[z];
    const float* __restrict__ bias = args.bias[z];
    const float* __restrict__ resid = args.resid[z];
    float* __restrict__ C = args.C[z];
    unsigned* __restrict__ Ctf = args.Ctf[z];
    const int K = args.K[z];
    const int T = K >> 5;

    const int m0 = blockIdx.y * 64;
    const int n0 = blockIdx.x * 64;

    unsigned* As = smem_dyn;
    unsigned* Ws = smem_dyn + NSTAGE * TILE_WORDS;

    const int tid  = threadIdx.x;
    const int lane = tid & 31;
    const int wid  = tid >> 5;
    const int wm   = (wid & 1) * 32;
    const int wn   = (wid >> 1) * 32;
    const int g    = lane >> 2;
    const int tg   = lane & 3;

    const int r0l = tid >> 3;
    const int ql  = tid & 7;

    unsigned sA_base, sW_base;
    {
        unsigned base = (unsigned)__cvta_generic_to_shared(smem_dyn);
        sA_base = base + (r0l * 36 + ql * 4) * 4;
        sW_base = base + (NSTAGE * TILE_WORDS + r0l * 36 + ql * 4) * 4;
    }

    float acc[2][4][4];
#pragma unroll
    for (int mt = 0; mt < 2; mt++)
#pragma unroll
        for (int nt = 0; nt < 4; nt++)
#pragma unroll
            for (int r = 0; r < 4; r++) acc[mt][nt][r] = 0.f;

    auto issue = [&](int t, int st) {
        const int k0 = t * 32 + ql * 4;
        const unsigned soffA = sA_base + st * TILE_WORDS * 4;
        const unsigned soffW = sW_base + st * TILE_WORDS * 4;
#pragma unroll
        for (int it = 0; it < 4; it++) {
            cp_async16(soffA + it * 16 * 36 * 4, A + (m0 + r0l + it * 16) * K + k0);
            cp_async16(soffW + it * 16 * 36 * 4, W + (n0 + r0l + it * 16) * K + k0);
        }
    };

    issue(0, 0); cp_commit();
    if (T > 1) issue(1, 1);
    cp_commit();

    int st = 0;
    for (int t = 0; t < T; t++) {
        cp_wait1();
        __syncthreads();

        if (t + 2 < T) issue(t + 2, (st + 2) % NSTAGE);
        cp_commit();

        const unsigned* Ab = As + st * TILE_WORDS;
        const unsigned* Wb = Ws + st * TILE_WORDS;

#pragma unroll
        for (int ks = 0; ks < 4; ks++) {
            const int kb = ks * 8;
            unsigned a[2][4], b[4][2];
#pragma unroll
            for (int mt = 0; mt < 2; mt++) {
                int row = wm + mt * 16 + g;
                a[mt][0] = Ab[row * 36 + kb + tg];
                a[mt][1] = Ab[(row + 8) * 36 + kb + tg];
                a[mt][2] = Ab[row * 36 + kb + tg + 4];
                a[mt][3] = Ab[(row + 8) * 36 + kb + tg + 4];
            }
#pragma unroll
            for (int nt = 0; nt < 4; nt++) {
                int n = wn + nt * 8 + g;
                b[nt][0] = Wb[n * 36 + kb + tg];
                b[nt][1] = Wb[n * 36 + kb + tg + 4];
            }
#pragma unroll
            for (int mt = 0; mt < 2; mt++)
#pragma unroll
                for (int nt = 0; nt < 4; nt++) {
                    asm volatile(
                        "mma.sync.aligned.m16n8k8.row.col.f32.tf32.tf32.f32 "
                        "{%0,%1,%2,%3}, {%4,%5,%6,%7}, {%8,%9}, {%0,%1,%2,%3};"
                        : "+f"(acc[mt][nt][0]), "+f"(acc[mt][nt][1]),
                          "+f"(acc[mt][nt][2]), "+f"(acc[mt][nt][3])
                        : "r"(a[mt][0]), "r"(a[mt][1]), "r"(a[mt][2]), "r"(a[mt][3]),
                          "r"(b[nt][0]), "r"(b[nt][1]));
                }
        }
        st = (st + 1) % NSTAGE;
    }

#pragma unroll
    for (int mt = 0; mt < 2; mt++) {
#pragma unroll
        for (int nt = 0; nt < 4; nt++) {
            int row0 = m0 + wm + mt * 16 + g;
            int col  = n0 + wn + nt * 8 + tg * 2;
            float b0 = bias[col], b1 = bias[col + 1];
            float2 v0 = make_float2(acc[mt][nt][0] + b0, acc[mt][nt][1] + b1);
            float2 v1 = make_float2(acc[mt][nt][2] + b0, acc[mt][nt][3] + b1);
            if (resid) {
                float2 r0 = *(const float2*)(resid + row0 * DM + col);
                float2 r1 = *(const float2*)(resid + (row0 + 8) * DM + col);
                v0.x += r0.x; v0.y += r0.y;
                v1.x += r1.x; v1.y += r1.y;
            }
            *(float2*)(C + row0 * DM + col)       = v0;
            *(float2*)(C + (row0 + 8) * DM + col) = v1;
            if (Ctf) {
                *(uint2*)(Ctf + row0 * DM + col) = make_uint2(f2tf32(v0.x), f2tf32(v0.y));
                *(uint2*)(Ctf + (row0 + 8) * DM + col) = make_uint2(f2tf32(v1.x), f2tf32(v1.y));
            }
        }
    }
}

// ---------------------------------------------------------------------------
// CTA-tiled sliding-window attention, 512 threads (16 warps).
// CTA = (64 queries, 1 head). Same algorithm/layout as R8, work split 2x finer.
// ---------------------------------------------------------------------------
#define KPAD 133
#define VPAD 136
#define QPAD 136
#define ATT_SMEM ((130 * VPAD + 64 * QPAD + 130 * KPAD) * 4)

extern __shared__ float att_sm[];

__global__ __launch_bounds__(512, 1) void swattn_tiled(
        const float* __restrict__ kb0, const float* __restrict__ vb0,
        const float* __restrict__ kb1, const float* __restrict__ vb1) {
    float* Vs = att_sm;                        // [130][136]  (float4, aligned)
    float* Qs = att_sm + 130 * VPAD;           // [64][136]   (float4, aligned)
    float* Ks = Qs + 64 * QPAD;                // [130][133]  (scalar only)
    float* S  = Qs;

    const int a  = blockIdx.z;
    const int h  = blockIdx.y;
    const int i0 = blockIdx.x * 64;
    const int idx0 = i0 - 32;
    const int tid = threadIdx.x;

    const float* __restrict__ Qg = g_Q[a];
    const float* __restrict__ Kg = g_K[a];
    const float* __restrict__ Vg = g_V[a];
    const float* __restrict__ kb = (a ? kb1 : kb0) + h * 128;
    const float* __restrict__ vb = (a ? vb1 : vb0) + h * 128;

    const float scale = 0.08838834764831845f;  // 1/sqrt(128)

    // ---- stage Q (64 x 128) ----
    for (int f = tid; f < 64 * 32; f += 512) {
        int r = f >> 5, c = f & 31;
        float4 v = *(const float4*)(Qg + (i0 + r) * DM + h * 128 + c * 4);
        *(float4*)(Qs + r * QPAD + c * 4) = v;
    }
    // ---- stage K and V bands (rows j=0..128 real, j=129 = kb/vb) ----
    for (int f = tid; f < 130 * 32; f += 512) {
        int j = f >> 5, c = f & 31;
        int gr = min(max(idx0 + j, 0), 511);
        const float* ksrc = (j < 129) ? Kg + gr * DM + h * 128 : kb;
        const float* vsrc = (j < 129) ? Vg + gr * DM + h * 128 : vb;
        float4 kv = *(const float4*)(ksrc + c * 4);
        float4 vv = *(const float4*)(vsrc + c * 4);
        Ks[j * KPAD + c * 4 + 0] = kv.x;
        Ks[j * KPAD + c * 4 + 1] = kv.y;
        Ks[j * KPAD + c * 4 + 2] = kv.z;
        Ks[j * KPAD + c * 4 + 3] = kv.w;
        *(float4*)(Vs + j * VPAD + c * 4) = vv;
    }
    __syncthreads();

    // ---- score GEMM: S[q][j] = Q[q] . Krow[j]; 2 queries x 6 j per thread ----
    {
        const int ty = tid >> 4;      // 0..31 -> q block of 2
        const int tx = tid & 15;
        const int qb = ty * 2;

        int  jidx[6];
        bool jok[6];
#pragma unroll
        for (int jj = 0; jj < 5; jj++) {
            jidx[jj] = qb + tx + 16 * jj;   // band [qb, qb+67] covered by 80
            jok[jj]  = (jidx[jj] < 130);
        }
        jidx[5] = 129; jok[5] = true;

        float acc[2][6];
#pragma unroll
        for (int qq = 0; qq < 2; qq++)
#pragma unroll
            for (int jj = 0; jj < 6; jj++) acc[qq][jj] = 0.f;

#pragma unroll 8
        for (int kk = 0; kk < 128; kk++) {
            float qv[2];
#pragma unroll
            for (int qq = 0; qq < 2; qq++) qv[qq] = Qs[(qb + qq) * QPAD + kk];
#pragma unroll
            for (int jj = 0; jj < 6; jj++) {
                if (jok[jj]) {
                    float kv = Ks[jidx[jj] * KPAD + kk];
#pragma unroll
                    for (int qq = 0; qq < 2; qq++) acc[qq][jj] += qv[qq] * kv;
                }
            }
        }
        __syncthreads();  // done reading Qs; S aliases it

#pragma unroll
        for (int jj = 0; jj < 6; jj++) {
            if (jok[jj] && (jj < 5 || tx == 0)) {
#pragma unroll
                for (int qq = 0; qq < 2; qq++)
                    S[(qb + qq) * QPAD + jidx[jj]] = acc[qq][jj] * scale;
            }
        }
    }
    __syncthreads();

    // ---- softmax per query (8 threads per query) ----
    {
        const int q = tid >> 3;
        const int s = tid & 7;
        const int i = i0 + q;
        const int p_start = max(0, 32 - i);
        const int p_end   = min(66, 544 - i);
        const int invalid = 66 - (p_end - p_start);
        const int n_pad   = max(0, invalid - 2);

        float vals[9];
        float m = -1e30f;
#pragma unroll
        for (int k = 0; k < 9; k++) {
            int p = s + 8 * k;
            bool valid = (p >= p_start) & (p < p_end);
            vals[k] = valid ? S[q * QPAD + q + p] : -1e30f;
            m = fmaxf(m, vals[k]);
        }
        float sp = S[q * QPAD + 129];
        if (n_pad > 0) m = fmaxf(m, sp);
        m = fmaxf(m, __shfl_xor_sync(0xffffffffu, m, 1));
        m = fmaxf(m, __shfl_xor_sync(0xffffffffu, m, 2));
        m = fmaxf(m, __shfl_xor_sync(0xffffffffu, m, 4));

        float d = 0.f;
#pragma unroll
        for (int k = 0; k < 9; k++) {
            int p = s + 8 * k;
            bool valid = (p >= p_start) & (p < p_end);
            float e = valid ? expf(vals[k] - m) : 0.f;
            vals[k] = e;
            d += e;
        }
        d += __shfl_xor_sync(0xffffffffu, d, 1);
        d += __shfl_xor_sync(0xffffffffu, d, 2);
        d += __shfl_xor_sync(0xffffffffu, d, 4);
        float wp = (n_pad > 0) ? (float)n_pad * expf(sp - m) : 0.f;
        const float inv = 1.f / (d + wp);

        __syncwarp();  // all group reads of S done before zeroing
        for (int c = s * 17; c < s * 17 + 17; c++) S[q * QPAD + c] = 0.f;
        __syncwarp();

#pragma unroll
        for (int k = 0; k < 9; k++) {
            int p = s + 8 * k;
            if ((p >= p_start) & (p < p_end)) S[q * QPAD + q + p] = vals[k] * inv;
        }
        if (s == 0) S[q * QPAD + 129] = wp * inv;
    }
    __syncthreads();

    // ---- V GEMM: O[q][d] = sum_j W[q][j] * V[j][d]; warp per 4 queries ----
    {
        const int wty  = tid >> 5;     // 0..15 -> 4 queries each
        const int lane = tid & 31;     // -> 4 dims
        const int qb0  = wty * 4;

        float4 acc[4];
#pragma unroll
        for (int qq = 0; qq < 4; qq++) acc[qq] = make_float4(0.f, 0.f, 0.f, 0.f);

        for (int j = qb0; j <= qb0 + 68; j++) {   // j <= 128 always
            float4 v4 = *(const float4*)(Vs + j * VPAD + lane * 4);
#pragma unroll
            for (int qq = 0; qq < 4; qq++) {
                float w = S[(qb0 + qq) * QPAD + j];
                acc[qq].x += w * v4.x; acc[qq].y += w * v4.y;
                acc[qq].z += w * v4.z; acc[qq].w += w * v4.w;
            }
        }
        {   // pad row j = 129
            float4 v4 = *(const float4*)(Vs + 129 * VPAD + lane * 4);
#pragma unroll
            for (int qq = 0; qq < 4; qq++) {
                float w = S[(qb0 + qq) * QPAD + 129];
                acc[qq].x += w * v4.x; acc[qq].y += w * v4.y;
                acc[qq].z += w * v4.z; acc[qq].w += w * v4.w;
            }
        }
#pragma unroll
        for (int qq = 0; qq < 4; qq++) {
            *(uint4*)(g_O_tf[a] + (i0 + qb0 + qq) * DM + h * 128 + lane * 4) = cvt4(acc[qq]);
        }
    }
}

// ---------------------------------------------------------------------------
extern "C" void kernel_launch(void* const* d_in, const int* in_sizes, int n_in,
                              void* d_out, int out_size) {
    (void)in_sizes; (void)n_in; (void)out_size;

    const float* images   = (const float*)d_in[0];
    const float* captions = (const float*)d_in[1];
    const float* tp_w = (const float*)d_in[3];
    const float* tp_b = (const float*)d_in[4];
    const float* ip_w = (const float*)d_in[5];
    const float* ip_b = (const float*)d_in[6];
    const float* ia[8]; for (int k = 0; k < 8; k++) ia[k] = (const float*)d_in[7 + k];
    const float* ta[8]; for (int k = 0; k < 8; k++) ta[k] = (const float*)d_in[15 + k];
    float* out = (float*)d_out;

    float *txt, *img, *Qb, *Kb, *Vb;
    unsigned *txt_tf, *img_tf, *Otf, *wtf, *cap_tf, *im_tf;
    cudaGetSymbolAddress((void**)&txt, g_txt);
    cudaGetSymbolAddress((void**)&img, g_img);
    cudaGetSymbolAddress((void**)&txt_tf, g_txt_tf);
    cudaGetSymbolAddress((void**)&img_tf, g_img_tf);
    cudaGetSymbolAddress((void**)&Qb, g_Q);
    cudaGetSymbolAddress((void**)&Kb, g_K);
    cudaGetSymbolAddress((void**)&Vb, g_V);
    cudaGetSymbolAddress((void**)&Otf, g_O_tf);
    cudaGetSymbolAddress((void**)&wtf, g_w_tf);
    cudaGetSymbolAddress((void**)&cap_tf, g_cap_tf);
    cudaGetSymbolAddress((void**)&im_tf, g_im_tf);

    unsigned* wts[10];
    for (int s = 0; s < 10; s++) wts[s] = wtf + s * (DM * DM);

    // ---- launch 0: bulk tf32 conversion ----
    {
        ConvArgs ca{};
        const float* srcs[12] = { tp_w, ip_w, ia[0], ia[2], ia[4], ia[6],
                                  ta[0], ta[2], ta[4], ta[6], captions, images };
        unsigned*    dsts[12] = { wts[0], wts[1], wts[2], wts[3], wts[4], wts[5],
                                  wts[6], wts[7], wts[8], wts[9], cap_tf, im_tf };
        int ns[12] = { DM * 768, DM * DM, DM * DM, DM * DM, DM * DM, DM * DM,
                       DM * DM, DM * DM, DM * DM, DM * DM, NQ * 768, NQ * DM };
        for (int s = 0; s < 12; s++) { ca.src[s] = srcs[s]; ca.dst[s] = dsts[s]; ca.n4[s] = ns[s] / 4; }
        conv_tf32_kernel<<<dim3(64, 12), 256>>>(ca);
    }

    const dim3 blk(128);
    const int GX = DM / 64;   // 16
    const int GY = NQ / 64;   // 8
    const int SMEM = NSTAGE * TILE_WORDS * 2 * 4;
    cudaFuncSetAttribute(gemm_tf32_kernel, cudaFuncAttributeMaxDynamicSharedMemorySize, SMEM);
    cudaFuncSetAttribute(swattn_tiled, cudaFuncAttributeMaxDynamicSharedMemorySize, ATT_SMEM);

    // ---- launch 1: input projections (z=2) ----
    {
        GemmArgs ar{};
        ar.A[0] = cap_tf; ar.W[0] = wts[0]; ar.bias[0] = tp_b; ar.resid[0] = nullptr;
        ar.C[0] = txt; ar.Ctf[0] = txt_tf; ar.K[0] = 768;
        ar.A[1] = im_tf;  ar.W[1] = wts[1]; ar.bias[1] = ip_b; ar.resid[1] = nullptr;
        ar.C[1] = img; ar.Ctf[1] = img_tf; ar.K[1] = 1024;
        gemm_tf32_kernel<<<dim3(GX, GY, 2), blk, SMEM>>>(ar);
    }

    // ---- launch 2: six QKV projections (z=6) ----
    {
        GemmArgs ar{};
        const unsigned* Aarr[6] = { img_tf, txt_tf, txt_tf, txt_tf, img_tf, img_tf };
        const unsigned* Warr[6] = { wts[2], wts[3], wts[4], wts[6], wts[7], wts[8] };
        const float*    Barr[6] = { ia[1], ia[3], ia[5], ta[1], ta[3], ta[5] };
        float*          Carr[6] = { Qb, Kb, Vb, Qb + NEL, Kb + NEL, Vb + NEL };
        for (int s = 0; s < 6; s++) {
            ar.A[s] = Aarr[s]; ar.W[s] = Warr[s]; ar.bias[s] = Barr[s];
            ar.resid[s] = nullptr; ar.C[s] = Carr[s]; ar.Ctf[s] = nullptr; ar.K[s] = 1024;
        }
        gemm_tf32_kernel<<<dim3(GX, GY, 6), blk, SMEM>>>(ar);
    }

    // ---- launch 3: CTA-tiled sliding-window attention (512 thr) ----
    swattn_tiled<<<dim3(8, 8, 2), 512, ATT_SMEM>>>(ia[3], ia[5], ta[3], ta[5]);

    // ---- launch 4: output projections + residual (z=2) ----
    {
        GemmArgs ar{};
        ar.A[0] = Otf;       ar.W[0] = wts[5]; ar.bias[0] = ia[7]; ar.resid[0] = img;
        ar.C[0] = out;       ar.Ctf[0] = nullptr; ar.K[0] = 1024;
        ar.A[1] = Otf + NEL; ar.W[1] = wts[9]; ar.bias[1] = ta[7]; ar.resid[1] = txt;
        ar.C[1] = out + NEL; ar.Ctf[1] = nullptr; ar.K[1] = 1024;
        gemm_tf32_kernel<<<dim3(GX, GY, 2), blk, SMEM>>>(ar);
    }
}

// round 10
// speedup vs baseline: 1.3290x; 1.0824x over previous
#include <cuda_runtime.h>
#include <cuda_bf16.h>
#include <math.h>

#define NQ 512
#define DM 1024
#define NEL (NQ * DM)

// ---------------- scratch ----------------
__device__ float    g_txt[NEL];           // f32 (residual)
__device__ float    g_img[NEL];
__device__ unsigned g_txt_tf[NEL];        // tf32 copies (GEMM A inputs)
__device__ unsigned g_img_tf[NEL];
__device__ float    g_Q[2][NEL];
__device__ float    g_K[2][NEL];
__device__ float    g_V[2][NEL];
__device__ unsigned g_O_tf[2][NEL];       // attention out, tf32
__device__ unsigned g_w_tf[10][DM * DM];
__device__ unsigned g_cap_tf[NQ * 768];
__device__ unsigned g_im_tf[NEL];

__device__ __forceinline__ unsigned f2tf32(float x) {
    unsigned u;
    asm("cvt.rna.tf32.f32 %0, %1;" : "=r"(u) : "f"(x));
    return u;
}
__device__ __forceinline__ uint4 cvt4(float4 v) {
    return make_uint4(f2tf32(v.x), f2tf32(v.y), f2tf32(v.z), f2tf32(v.w));
}

// ---------------- bulk f32 -> tf32 conversion ----------------
struct ConvArgs {
    const float* src[12];
    unsigned*    dst[12];
    int          n4[12];
};

__global__ __launch_bounds__(256) void conv_tf32_kernel(ConvArgs a) {
    const int z = blockIdx.y;
    const float4* __restrict__ s = (const float4*)a.src[z];
    uint4* __restrict__ d = (uint4*)a.dst[z];
    const int n4 = a.n4[z];
    for (int i = blockIdx.x * blockDim.x + threadIdx.x; i < n4; i += gridDim.x * blockDim.x)
        d[i] = cvt4(s[i]);
}

// ---------------------------------------------------------------------------
// tf32 GEMM (pre-converted inputs): C = A(512xK) @ W(1024xK)^T + bias (+resid)
// BM=128, BN=64, BK=32, 256 threads (8 warps, 4Mx2N, warp tile 32x32).
// cp.async 3-stage pipeline, one __syncthreads per K-iter.
// ---------------------------------------------------------------------------
struct GemmArgs {
    const unsigned* A[6];
    const unsigned* W[6];
    const float*    bias[6];
    const float*    resid[6];
    float*          C[6];
    unsigned*       Ctf[6];
    int             K[6];
};

#define NSTAGE 3
#define A_TW (128 * 36)
#define W_TW (64 * 36)
#define GEMM_SMEM ((A_TW + W_TW) * NSTAGE * 4)

__device__ __forceinline__ void cp_async16(unsigned smem_addr, const void* gptr) {
    asm volatile("cp.async.cg.shared.global [%0], [%1], 16;" :: "r"(smem_addr), "l"(gptr));
}
__device__ __forceinline__ void cp_commit() { asm volatile("cp.async.commit_group;"); }
__device__ __forceinline__ void cp_wait1()  { asm volatile("cp.async.wait_group 1;"); }

extern __shared__ unsigned smem_dyn[];

__global__ __launch_bounds__(256) void gemm_tf32_kernel(GemmArgs args) {
    const int z = blockIdx.z;
    const unsigned* __restrict__ A = args.A[z];
    const unsigned* __restrict__ W = args.W[z];
    const float* __restrict__ bias = args.bias[z];
    const float* __restrict__ resid = args.resid[z];
    float* __restrict__ C = args.C[z];
    unsigned* __restrict__ Ctf = args.Ctf[z];
    const int K = args.K[z];
    const int T = K >> 5;

    const int m0 = blockIdx.y * 128;
    const int n0 = blockIdx.x * 64;

    unsigned* As = smem_dyn;                   // [NSTAGE][128][36]
    unsigned* Ws = smem_dyn + NSTAGE * A_TW;   // [NSTAGE][64][36]

    const int tid  = threadIdx.x;
    const int lane = tid & 31;
    const int wid  = tid >> 5;
    const int wm   = (wid & 3) * 32;
    const int wn   = (wid >> 2) * 32;
    const int g    = lane >> 2;
    const int tg   = lane & 3;

    const int rl = tid >> 3;       // load row base (A: +32/it x4; W: +32/it x2)
    const int ql = tid & 7;        // 16B chunk in row

    unsigned sA_base, sW_base;
    {
        unsigned base = (unsigned)__cvta_generic_to_shared(smem_dyn);
        sA_base = base + (rl * 36 + ql * 4) * 4;
        sW_base = base + (NSTAGE * A_TW + rl * 36 + ql * 4) * 4;
    }

    float acc[2][4][4];
#pragma unroll
    for (int mt = 0; mt < 2; mt++)
#pragma unroll
        for (int nt = 0; nt < 4; nt++)
#pragma unroll
            for (int r = 0; r < 4; r++) acc[mt][nt][r] = 0.f;

    auto issue = [&](int t, int st) {
        const int k0 = t * 32 + ql * 4;
        const unsigned soffA = sA_base + st * A_TW * 4;
        const unsigned soffW = sW_base + st * W_TW * 4;
#pragma unroll
        for (int it = 0; it < 4; it++)
            cp_async16(soffA + it * 32 * 36 * 4, A + (m0 + rl + it * 32) * K + k0);
#pragma unroll
        for (int it = 0; it < 2; it++)
            cp_async16(soffW + it * 32 * 36 * 4, W + (n0 + rl + it * 32) * K + k0);
    };

    issue(0, 0); cp_commit();
    if (T > 1) issue(1, 1);
    cp_commit();

    int st = 0;
    for (int t = 0; t < T; t++) {
        cp_wait1();
        __syncthreads();

        if (t + 2 < T) issue(t + 2, (st + 2) % NSTAGE);
        cp_commit();

        const unsigned* Ab = As + st * A_TW;
        const unsigned* Wb = Ws + st * W_TW;

#pragma unroll
        for (int ks = 0; ks < 4; ks++) {
            const int kb = ks * 8;
            unsigned a[2][4], b[4][2];
#pragma unroll
            for (int mt = 0; mt < 2; mt++) {
                int row = wm + mt * 16 + g;
                a[mt][0] = Ab[row * 36 + kb + tg];
                a[mt][1] = Ab[(row + 8) * 36 + kb + tg];
                a[mt][2] = Ab[row * 36 + kb + tg + 4];
                a[mt][3] = Ab[(row + 8) * 36 + kb + tg + 4];
            }
#pragma unroll
            for (int nt = 0; nt < 4; nt++) {
                int n = wn + nt * 8 + g;
                b[nt][0] = Wb[n * 36 + kb + tg];
                b[nt][1] = Wb[n * 36 + kb + tg + 4];
            }
#pragma unroll
            for (int mt = 0; mt < 2; mt++)
#pragma unroll
                for (int nt = 0; nt < 4; nt++) {
                    asm volatile(
                        "mma.sync.aligned.m16n8k8.row.col.f32.tf32.tf32.f32 "
                        "{%0,%1,%2,%3}, {%4,%5,%6,%7}, {%8,%9}, {%0,%1,%2,%3};"
                        : "+f"(acc[mt][nt][0]), "+f"(acc[mt][nt][1]),
                          "+f"(acc[mt][nt][2]), "+f"(acc[mt][nt][3])
                        : "r"(a[mt][0]), "r"(a[mt][1]), "r"(a[mt][2]), "r"(a[mt][3]),
                          "r"(b[nt][0]), "r"(b[nt][1]));
                }
        }
        st = (st + 1) % NSTAGE;
    }

#pragma unroll
    for (int mt = 0; mt < 2; mt++) {
#pragma unroll
        for (int nt = 0; nt < 4; nt++) {
            int row0 = m0 + wm + mt * 16 + g;
            int col  = n0 + wn + nt * 8 + tg * 2;
            float b0 = bias[col], b1 = bias[col + 1];
            float2 v0 = make_float2(acc[mt][nt][0] + b0, acc[mt][nt][1] + b1);
            float2 v1 = make_float2(acc[mt][nt][2] + b0, acc[mt][nt][3] + b1);
            if (resid) {
                float2 r0 = *(const float2*)(resid + row0 * DM + col);
                float2 r1 = *(const float2*)(resid + (row0 + 8) * DM + col);
                v0.x += r0.x; v0.y += r0.y;
                v1.x += r1.x; v1.y += r1.y;
            }
            *(float2*)(C + row0 * DM + col)       = v0;
            *(float2*)(C + (row0 + 8) * DM + col) = v1;
            if (Ctf) {
                *(uint2*)(Ctf + row0 * DM + col) = make_uint2(f2tf32(v0.x), f2tf32(v0.y));
                *(uint2*)(Ctf + (row0 + 8) * DM + col) = make_uint2(f2tf32(v1.x), f2tf32(v1.y));
            }
        }
    }
}

// ---------------------------------------------------------------------------
// CTA-tiled sliding-window attention, 512 threads (16 warps).
// ---------------------------------------------------------------------------
#define KPAD 133
#define VPAD 136
#define QPAD 136
#define ATT_SMEM ((130 * VPAD + 64 * QPAD + 130 * KPAD) * 4)

extern __shared__ float att_sm[];

__global__ __launch_bounds__(512, 1) void swattn_tiled(
        const float* __restrict__ kb0, const float* __restrict__ vb0,
        const float* __restrict__ kb1, const float* __restrict__ vb1) {
    float* Vs = att_sm;                        // [130][136]  (float4, aligned)
    float* Qs = att_sm + 130 * VPAD;           // [64][136]   (float4, aligned)
    float* Ks = Qs + 64 * QPAD;                // [130][133]  (scalar only)
    float* S  = Qs;

    const int a  = blockIdx.z;
    const int h  = blockIdx.y;
    const int i0 = blockIdx.x * 64;
    const int idx0 = i0 - 32;
    const int tid = threadIdx.x;

    const float* __restrict__ Qg = g_Q[a];
    const float* __restrict__ Kg = g_K[a];
    const float* __restrict__ Vg = g_V[a];
    const float* __restrict__ kb = (a ? kb1 : kb0) + h * 128;
    const float* __restrict__ vb = (a ? vb1 : vb0) + h * 128;

    const float scale = 0.08838834764831845f;  // 1/sqrt(128)

    for (int f = tid; f < 64 * 32; f += 512) {
        int r = f >> 5, c = f & 31;
        float4 v = *(const float4*)(Qg + (i0 + r) * DM + h * 128 + c * 4);
        *(float4*)(Qs + r * QPAD + c * 4) = v;
    }
    for (int f = tid; f < 130 * 32; f += 512) {
        int j = f >> 5, c = f & 31;
        int gr = min(max(idx0 + j, 0), 511);
        const float* ksrc = (j < 129) ? Kg + gr * DM + h * 128 : kb;
        const float* vsrc = (j < 129) ? Vg + gr * DM + h * 128 : vb;
        float4 kv = *(const float4*)(ksrc + c * 4);
        float4 vv = *(const float4*)(vsrc + c * 4);
        Ks[j * KPAD + c * 4 + 0] = kv.x;
        Ks[j * KPAD + c * 4 + 1] = kv.y;
        Ks[j * KPAD + c * 4 + 2] = kv.z;
        Ks[j * KPAD + c * 4 + 3] = kv.w;
        *(float4*)(Vs + j * VPAD + c * 4) = vv;
    }
    __syncthreads();

    // ---- score GEMM ----
    {
        const int ty = tid >> 4;
        const int tx = tid & 15;
        const int qb = ty * 2;

        int  jidx[6];
        bool jok[6];
#pragma unroll
        for (int jj = 0; jj < 5; jj++) {
            jidx[jj] = qb + tx + 16 * jj;
            jok[jj]  = (jidx[jj] < 130);
        }
        jidx[5] = 129; jok[5] = true;

        float acc[2][6];
#pragma unroll
        for (int qq = 0; qq < 2; qq++)
#pragma unroll
            for (int jj = 0; jj < 6; jj++) acc[qq][jj] = 0.f;

#pragma unroll 8
        for (int kk = 0; kk < 128; kk++) {
            float qv[2];
#pragma unroll
            for (int qq = 0; qq < 2; qq++) qv[qq] = Qs[(qb + qq) * QPAD + kk];
#pragma unroll
            for (int jj = 0; jj < 6; jj++) {
                if (jok[jj]) {
                    float kv = Ks[jidx[jj] * KPAD + kk];
#pragma unroll
                    for (int qq = 0; qq < 2; qq++) acc[qq][jj] += qv[qq] * kv;
                }
            }
        }
        __syncthreads();

#pragma unroll
        for (int jj = 0; jj < 6; jj++) {
            if (jok[jj] && (jj < 5 || tx == 0)) {
#pragma unroll
                for (int qq = 0; qq < 2; qq++)
                    S[(qb + qq) * QPAD + jidx[jj]] = acc[qq][jj] * scale;
            }
        }
    }
    __syncthreads();

    // ---- softmax per query (8 threads per query) ----
    {
        const int q = tid >> 3;
        const int s = tid & 7;
        const int i = i0 + q;
        const int p_start = max(0, 32 - i);
        const int p_end   = min(66, 544 - i);
        const int invalid = 66 - (p_end - p_start);
        const int n_pad   = max(0, invalid - 2);

        float vals[9];
        float m = -1e30f;
#pragma unroll
        for (int k = 0; k < 9; k++) {
            int p = s + 8 * k;
            bool valid = (p >= p_start) & (p < p_end);
            vals[k] = valid ? S[q * QPAD + q + p] : -1e30f;
            m = fmaxf(m, vals[k]);
        }
        float sp = S[q * QPAD + 129];
        if (n_pad > 0) m = fmaxf(m, sp);
        m = fmaxf(m, __shfl_xor_sync(0xffffffffu, m, 1));
        m = fmaxf(m, __shfl_xor_sync(0xffffffffu, m, 2));
        m = fmaxf(m, __shfl_xor_sync(0xffffffffu, m, 4));

        float d = 0.f;
#pragma unroll
        for (int k = 0; k < 9; k++) {
            int p = s + 8 * k;
            bool valid = (p >= p_start) & (p < p_end);
            float e = valid ? expf(vals[k] - m) : 0.f;
            vals[k] = e;
            d += e;
        }
        d += __shfl_xor_sync(0xffffffffu, d, 1);
        d += __shfl_xor_sync(0xffffffffu, d, 2);
        d += __shfl_xor_sync(0xffffffffu, d, 4);
        float wp = (n_pad > 0) ? (float)n_pad * expf(sp - m) : 0.f;
        const float inv = 1.f / (d + wp);

        __syncwarp();
        for (int c = s * 17; c < s * 17 + 17; c++) S[q * QPAD + c] = 0.f;
        __syncwarp();

#pragma unroll
        for (int k = 0; k < 9; k++) {
            int p = s + 8 * k;
            if ((p >= p_start) & (p < p_end)) S[q * QPAD + q + p] = vals[k] * inv;
        }
        if (s == 0) S[q * QPAD + 129] = wp * inv;
    }
    __syncthreads();

    // ---- V GEMM ----
    {
        const int wty  = tid >> 5;
        const int lane = tid & 31;
        const int qb0  = wty * 4;

        float4 acc[4];
#pragma unroll
        for (int qq = 0; qq < 4; qq++) acc[qq] = make_float4(0.f, 0.f, 0.f, 0.f);

        for (int j = qb0; j <= qb0 + 68; j++) {
            float4 v4 = *(const float4*)(Vs + j * VPAD + lane * 4);
#pragma unroll
            for (int qq = 0; qq < 4; qq++) {
                float w = S[(qb0 + qq) * QPAD + j];
                acc[qq].x += w * v4.x; acc[qq].y += w * v4.y;
                acc[qq].z += w * v4.z; acc[qq].w += w * v4.w;
            }
        }
        {
            float4 v4 = *(const float4*)(Vs + 129 * VPAD + lane * 4);
#pragma unroll
            for (int qq = 0; qq < 4; qq++) {
                float w = S[(qb0 + qq) * QPAD + 129];
                acc[qq].x += w * v4.x; acc[qq].y += w * v4.y;
                acc[qq].z += w * v4.z; acc[qq].w += w * v4.w;
            }
        }
#pragma unroll
        for (int qq = 0; qq < 4; qq++) {
            *(uint4*)(g_O_tf[a] + (i0 + qb0 + qq) * DM + h * 128 + lane * 4) = cvt4(acc[qq]);
        }
    }
}

// ---------------------------------------------------------------------------
extern "C" void kernel_launch(void* const* d_in, const int* in_sizes, int n_in,
                              void* d_out, int out_size) {
    (void)in_sizes; (void)n_in; (void)out_size;

    const float* images   = (const float*)d_in[0];
    const float* captions = (const float*)d_in[1];
    const float* tp_w = (const float*)d_in[3];
    const float* tp_b = (const float*)d_in[4];
    const float* ip_w = (const float*)d_in[5];
    const float* ip_b = (const float*)d_in[6];
    const float* ia[8]; for (int k = 0; k < 8; k++) ia[k] = (const float*)d_in[7 + k];
    const float* ta[8]; for (int k = 0; k < 8; k++) ta[k] = (const float*)d_in[15 + k];
    float* out = (float*)d_out;

    float *txt, *img, *Qb, *Kb, *Vb;
    unsigned *txt_tf, *img_tf, *Otf, *wtf, *cap_tf, *im_tf;
    cudaGetSymbolAddress((void**)&txt, g_txt);
    cudaGetSymbolAddress((void**)&img, g_img);
    cudaGetSymbolAddress((void**)&txt_tf, g_txt_tf);
    cudaGetSymbolAddress((void**)&img_tf, g_img_tf);
    cudaGetSymbolAddress((void**)&Qb, g_Q);
    cudaGetSymbolAddress((void**)&Kb, g_K);
    cudaGetSymbolAddress((void**)&Vb, g_V);
    cudaGetSymbolAddress((void**)&Otf, g_O_tf);
    cudaGetSymbolAddress((void**)&wtf, g_w_tf);
    cudaGetSymbolAddress((void**)&cap_tf, g_cap_tf);
    cudaGetSymbolAddress((void**)&im_tf, g_im_tf);

    unsigned* wts[10];
    for (int s = 0; s < 10; s++) wts[s] = wtf + s * (DM * DM);

    // ---- launch 0: bulk tf32 conversion ----
    {
        ConvArgs ca{};
        const float* srcs[12] = { tp_w, ip_w, ia[0], ia[2], ia[4], ia[6],
                                  ta[0], ta[2], ta[4], ta[6], captions, images };
        unsigned*    dsts[12] = { wts[0], wts[1], wts[2], wts[3], wts[4], wts[5],
                                  wts[6], wts[7], wts[8], wts[9], cap_tf, im_tf };
        int ns[12] = { DM * 768, DM * DM, DM * DM, DM * DM, DM * DM, DM * DM,
                       DM * DM, DM * DM, DM * DM, DM * DM, NQ * 768, NQ * DM };
        for (int s = 0; s < 12; s++) { ca.src[s] = srcs[s]; ca.dst[s] = dsts[s]; ca.n4[s] = ns[s] / 4; }
        conv_tf32_kernel<<<dim3(64, 12), 256>>>(ca);
    }

    const dim3 blk(256);
    const int GX = DM / 64;    // 16
    const int GY = NQ / 128;   // 4
    cudaFuncSetAttribute(gemm_tf32_kernel, cudaFuncAttributeMaxDynamicSharedMemorySize, GEMM_SMEM);
    cudaFuncSetAttribute(swattn_tiled, cudaFuncAttributeMaxDynamicSharedMemorySize, ATT_SMEM);

    // ---- launch 1: input projections (z=2) ----
    {
        GemmArgs ar{};
        ar.A[0] = cap_tf; ar.W[0] = wts[0]; ar.bias[0] = tp_b; ar.resid[0] = nullptr;
        ar.C[0] = txt; ar.Ctf[0] = txt_tf; ar.K[0] = 768;
        ar.A[1] = im_tf;  ar.W[1] = wts[1]; ar.bias[1] = ip_b; ar.resid[1] = nullptr;
        ar.C[1] = img; ar.Ctf[1] = img_tf; ar.K[1] = 1024;
        gemm_tf32_kernel<<<dim3(GX, GY, 2), blk, GEMM_SMEM>>>(ar);
    }

    // ---- launch 2: six QKV projections (z=6) ----
    {
        GemmArgs ar{};
        const unsigned* Aarr[6] = { img_tf, txt_tf, txt_tf, txt_tf, img_tf, img_tf };
        const unsigned* Warr[6] = { wts[2], wts[3], wts[4], wts[6], wts[7], wts[8] };
        const float*    Barr[6] = { ia[1], ia[3], ia[5], ta[1], ta[3], ta[5] };
        float*          Carr[6] = { Qb, Kb, Vb, Qb + NEL, Kb + NEL, Vb + NEL };
        for (int s = 0; s < 6; s++) {
            ar.A[s] = Aarr[s]; ar.W[s] = Warr[s]; ar.bias[s] = Barr[s];
            ar.resid[s] = nullptr; ar.C[s] = Carr[s]; ar.Ctf[s] = nullptr; ar.K[s] = 1024;
        }
        gemm_tf32_kernel<<<dim3(GX, GY, 6), blk, GEMM_SMEM>>>(ar);
    }

    // ---- launch 3: CTA-tiled sliding-window attention (512 thr) ----
    swattn_tiled<<<dim3(8, 8, 2), 512, ATT_SMEM>>>(ia[3], ia[5], ta[3], ta[5]);

    // ---- launch 4: output projections + residual (z=2) ----
    {
        GemmArgs ar{};
        ar.A[0] = Otf;       ar.W[0] = wts[5]; ar.bias[0] = ia[7]; ar.resid[0] = img;
        ar.C[0] = out;       ar.Ctf[0] = nullptr; ar.K[0] = 1024;
        ar.A[1] = Otf + NEL; ar.W[1] = wts[9]; ar.bias[1] = ta[7]; ar.resid[1] = txt;
        ar.C[1] = out + NEL; ar.Ctf[1] = nullptr; ar.K[1] = 1024;
        gemm_tf32_kernel<<<dim3(GX, GY, 2), blk, GEMM_SMEM>>>(ar);
    }
}